// round 15
// baseline (speedup 1.0000x reference)
#include <cuda_runtime.h>
#include <cuda_fp16.h>
#include <cstdint>
#include <math.h>

#define MTOK 16384
#define NOUT 512
#define KIN  1024
#define NTASKS 3
#define NEXP 10

// ---------------- scratch (device globals; no allocations allowed) ----------
__device__ __half g_S[(size_t)4 * MTOK * NOUT];           // shared-expert outs (fp16)
__device__ __half g_T[(size_t)6 * MTOK * NOUT];           // task-expert outs (fp16)
__device__ float g_G[(size_t)NTASKS * MTOK * 6];          // softmaxed gates
__device__ __half g_W16[(size_t)NEXP * NOUT * KIN];       // W^T fp16, [e][n][k]
__device__ __half g_A16[(size_t)NTASKS * MTOK * KIN];     // A fp16, [t][m][k]

// ---------------- helpers ----------------------------------------------------
__device__ __forceinline__ uint32_t smem_u32(const void* p) {
    uint32_t a;
    asm("{ .reg .u64 t; cvta.to.shared.u64 t, %1; cvt.u32.u64 %0, t; }"
        : "=r"(a) : "l"(p));
    return a;
}
__device__ __forceinline__ uint32_t SW128(uint32_t o) { return o ^ ((o >> 3) & 0x70); }

__device__ __forceinline__ void cp_async16(uint32_t dst, const void* src) {
    asm volatile("cp.async.cg.shared.global [%0], [%1], 16;"
                 :: "r"(dst), "l"(src) : "memory");
}
#define CP_COMMIT() asm volatile("cp.async.commit_group;" ::: "memory")
#define CP_WAIT2()  asm volatile("cp.async.wait_group 2;" ::: "memory")

__device__ __forceinline__ void ldm_x4(uint32_t* r, uint32_t addr) {
    asm volatile("ldmatrix.sync.aligned.m8n8.x4.shared.b16 {%0,%1,%2,%3}, [%4];"
                 : "=r"(r[0]), "=r"(r[1]), "=r"(r[2]), "=r"(r[3]) : "r"(addr));
}
__device__ __forceinline__ void mma_f16(float* c, const uint32_t* a, const uint32_t* b) {
    asm volatile("mma.sync.aligned.m16n8k16.row.col.f32.f16.f16.f32 "
                 "{%0,%1,%2,%3}, {%4,%5,%6,%7}, {%8,%9}, {%0,%1,%2,%3};"
                 : "+f"(c[0]), "+f"(c[1]), "+f"(c[2]), "+f"(c[3])
                 : "r"(a[0]), "r"(a[1]), "r"(a[2]), "r"(a[3]), "r"(b[0]), "r"(b[1]));
}

// ---------------- A prep: fp32 -> fp16 ---------------------------------------
__global__ __launch_bounds__(256)
void aprep_kernel(const float* __restrict__ task_inputs)
{
    const size_t i = ((size_t)blockIdx.x * 256 + threadIdx.x) * 8;
    float4 v0 = *(const float4*)(task_inputs + i);
    float4 v1 = *(const float4*)(task_inputs + i + 4);
    __half2 h0 = __floats2half2_rn(v0.x, v0.y);
    __half2 h1 = __floats2half2_rn(v0.z, v0.w);
    __half2 h2 = __floats2half2_rn(v1.x, v1.y);
    __half2 h3 = __floats2half2_rn(v1.z, v1.w);
    uint4 packed = make_uint4(*(uint32_t*)&h0, *(uint32_t*)&h1,
                              *(uint32_t*)&h2, *(uint32_t*)&h3);
    *(uint4*)(g_A16 + i) = packed;
}

// ---------------- W prep: transpose + fp16 -----------------------------------
__global__ __launch_bounds__(256)
void wprep_kernel(const float* __restrict__ shared_W, const float* __restrict__ task_W)
{
    __shared__ float tile[32][33];
    const int e = blockIdx.z;
    const float* W = (e < 4) ? shared_W + (size_t)e * KIN * NOUT
                             : task_W + (size_t)(e - 4) * KIN * NOUT;
    const int k0 = blockIdx.x * 32, n0 = blockIdx.y * 32;
    const int tx = threadIdx.x & 31, ty = threadIdx.x >> 5;

    #pragma unroll
    for (int i = 0; i < 4; i++)
        tile[ty + i * 8][tx] = W[(size_t)(k0 + ty + i * 8) * NOUT + n0 + tx];
    __syncthreads();
    #pragma unroll
    for (int i = 0; i < 4; i++) {
        size_t idx = ((size_t)e * NOUT + (n0 + ty + i * 8)) * KIN + k0 + tx;
        g_W16[idx] = __float2half_rn(tile[tx][ty + i * 8]);
    }
}

// ---------------- fused GEMM (z<10) + gates (z==10) --------------------------
// GEMM: 128x256 CTA tile fp16, BK=64, 512 threads (16 warps, warp tile 32x64),
// 4 stages + wait_group 2, B-fragment double buffer across ks.
#define BM 128
#define BN 256
#define BK 64
#define NKT (KIN / BK)     // 16
#define ST_A 0
#define ST_B 16384
#define STAGE_SZ 49152
#define NSTAGE 4
#define SMEM_BYTES (NSTAGE * STAGE_SZ + 1024)

__global__ __launch_bounds__(512, 1)
void gemm_mma_kernel(const float* __restrict__ task_inputs,
                     const float* __restrict__ shared_b,
                     const float* __restrict__ task_b,
                     const float* __restrict__ gate_W,
                     const float* __restrict__ gate_b)
{
    extern __shared__ char dsm[];
    __shared__ float sbias[BN];

    const int tid = threadIdx.x;
    const int warp = tid >> 5;
    const int lane = tid & 31;
    const int z = blockIdx.z;

    // ======================= gate path (z == 10) ============================
    if (z == 10) {
        float* Wg = (float*)dsm;                       // [KIN][9] padded
        const int blk = blockIdx.y * gridDim.x + blockIdx.x;   // 0..255
        #pragma unroll 1
        for (int t = 0; t < NTASKS; t++) {
            __syncthreads();
            for (int i = tid; i < KIN * 6; i += 512)
                Wg[(i / 6) * 9 + (i % 6)] = gate_W[(size_t)t * KIN * 6 + i];
            __syncthreads();

            #pragma unroll 1
            for (int w = 0; w < 4; w++) {
                const int b = blk * 64 + warp * 4 + w;
                const float* x = task_inputs + ((size_t)t * MTOK + b) * KIN;

                float s[6] = {0.f, 0.f, 0.f, 0.f, 0.f, 0.f};
                #pragma unroll
                for (int i = 0; i < 8; i++) {
                    const int k = i * 128 + lane * 4;
                    float4 xv = *(const float4*)(x + k);
                    float xa[4] = {xv.x, xv.y, xv.z, xv.w};
                    #pragma unroll
                    for (int j = 0; j < 4; j++)
                        #pragma unroll
                        for (int e = 0; e < 6; e++)
                            s[e] = fmaf(xa[j], Wg[(k + j) * 9 + e], s[e]);
                }
                #pragma unroll
                for (int off = 16; off > 0; off >>= 1)
                    #pragma unroll
                    for (int e = 0; e < 6; e++)
                        s[e] += __shfl_xor_sync(0xffffffffu, s[e], off);

                if (lane == 0) {
                    float l[6], mx = -1e30f;
                    #pragma unroll
                    for (int e = 0; e < 6; e++) { l[e] = s[e] + gate_b[t * 6 + e]; mx = fmaxf(mx, l[e]); }
                    float sum = 0.f;
                    #pragma unroll
                    for (int e = 0; e < 6; e++) { l[e] = __expf(l[e] - mx); sum += l[e]; }
                    float inv = 1.f / sum;
                    float* gp = g_G + ((size_t)t * MTOK + b) * 6;
                    #pragma unroll
                    for (int e = 0; e < 6; e++) gp[e] = l[e] * inv;
                }
            }
        }
        return;
    }

    // ======================= GEMM path (z < 10) =============================
    const uint32_t raw = smem_u32(dsm);
    const uint32_t sb = (raw + 1023u) & ~1023u;

    const int bm0 = blockIdx.y * BM;
    const int bn0 = blockIdx.x * BN;

    size_t a_base;
    const float* bias;
    __half* out;
    if (z < 4) {
        a_base = 0;                                  // shared experts: task 0
        bias = shared_b + z * NOUT;
        out = g_S + (size_t)z * MTOK * NOUT;
    } else {
        const int j = z - 4;
        a_base = (size_t)(j >> 1) * MTOK * KIN;
        bias = task_b + j * NOUT;
        out = g_T + (size_t)j * MTOK * NOUT;
    }
    const __half* A = g_A16 + a_base;
    const __half* W = g_W16 + ((size_t)z * NOUT + bn0) * KIN;

    if (tid < BN) sbias[tid] = bias[bn0 + tid];

    // ---- staging: A 16KB (1024 x 16B chunks, 2/thr), B 32KB (2048, 4/thr) --
    uint32_t a_soff[2];
    const __half* a_src[2];
    #pragma unroll
    for (int i = 0; i < 2; i++) {
        int c = tid + 512 * i;
        int row = c >> 3, seg = c & 7;
        a_soff[i] = SW128((uint32_t)(row * 128 + seg * 16));
        a_src[i] = A + (size_t)(bm0 + row) * KIN + seg * 8;
    }
    uint32_t b_soff[4];
    const __half* b_src[4];
    #pragma unroll
    for (int i = 0; i < 4; i++) {
        int c = tid + 512 * i;
        int row = c >> 3, seg = c & 7;
        b_soff[i] = SW128((uint32_t)(row * 128 + seg * 16));
        b_src[i] = W + (size_t)row * KIN + seg * 8;
    }

    // warp tiling: 4(M) x 4(N); warp tile 32x64
    const int wm = warp & 3, wn = warp >> 2;
    const int m_base = wm * 32;
    const int n_base = wn * 64;
    const int lr16 = lane & 15, lc16 = (lane >> 4) << 4;

    uint32_t a_lbase[2];
    #pragma unroll
    for (int mf = 0; mf < 2; mf++)
        a_lbase[mf] = (uint32_t)((m_base + mf * 16 + lr16) * 128 + lc16);
    uint32_t b_lbase[4];
    #pragma unroll
    for (int p = 0; p < 4; p++)
        b_lbase[p] = (uint32_t)((n_base + p * 16 + lr16) * 128 + lc16);

    float acc[2][8][4];
    #pragma unroll
    for (int mf = 0; mf < 2; mf++)
        #pragma unroll
        for (int nf = 0; nf < 8; nf++)
            #pragma unroll
            for (int r = 0; r < 4; r++) acc[mf][nf][r] = 0.f;

    auto issue = [&](int kt, int s) {
        const uint32_t sa = sb + s * STAGE_SZ;
        const int ko = kt * BK;
        #pragma unroll
        for (int i = 0; i < 2; i++)
            cp_async16(sa + ST_A + a_soff[i], a_src[i] + ko);
        #pragma unroll
        for (int i = 0; i < 4; i++)
            cp_async16(sa + ST_B + b_soff[i], b_src[i] + ko);
    };

    issue(0, 0); CP_COMMIT();
    issue(1, 1); CP_COMMIT();
    issue(2, 2); CP_COMMIT();

    #pragma unroll 1
    for (int kt = 0; kt < NKT; kt++) {
        CP_WAIT2();
        __syncthreads();

        if (kt + 3 < NKT) issue(kt + 3, (kt + 3) & 3);
        CP_COMMIT();

        const uint32_t ab = sb + (kt & 3) * STAGE_SZ;

        // B-fragment double buffer across ks. b16 ldmatrix reg->fragment map:
        //   n8-block even = {r0, r2}, n8-block odd = {r1, r3}  (validated R6/R13)
        uint32_t bfr[2][8][2];
        {
            #pragma unroll
            for (int p = 0; p < 4; p++) {
                uint32_t r[4];
                ldm_x4(r, ab + ST_B + SW128(b_lbase[p]));
                bfr[0][2 * p][0] = r[0];     bfr[0][2 * p + 1][0] = r[1];
                bfr[0][2 * p][1] = r[2];     bfr[0][2 * p + 1][1] = r[3];
            }
        }
        #pragma unroll
        for (int ks = 0; ks < 4; ks++) {
            const int cur = ks & 1;
            if (ks < 3) {
                const int nx = cur ^ 1;
                #pragma unroll
                for (int p = 0; p < 4; p++) {
                    uint32_t r[4];
                    ldm_x4(r, ab + ST_B + SW128(b_lbase[p] + (ks + 1) * 32));
                    bfr[nx][2 * p][0] = r[0];     bfr[nx][2 * p + 1][0] = r[1];
                    bfr[nx][2 * p][1] = r[2];     bfr[nx][2 * p + 1][1] = r[3];
                }
            }
            #pragma unroll
            for (int mf = 0; mf < 2; mf++) {
                uint32_t afr[4];
                ldm_x4(afr, ab + ST_A + SW128(a_lbase[mf] + ks * 32));
                #pragma unroll
                for (int nf = 0; nf < 8; nf++)
                    mma_f16(acc[mf][nf], afr, bfr[cur][nf]);
            }
        }
    }

    // ---- epilogue: bias + relu + fp16 store ----
    const int gq = lane >> 2, i2 = (lane & 3) * 2;
    #pragma unroll
    for (int mf = 0; mf < 2; mf++) {
        const int r0 = bm0 + m_base + mf * 16 + gq;
        #pragma unroll
        for (int nf = 0; nf < 8; nf++) {
            const int cl = n_base + nf * 8 + i2;
            const float b0 = sbias[cl], b1 = sbias[cl + 1];
            __half2 v0 = __floats2half2_rn(fmaxf(acc[mf][nf][0] + b0, 0.f),
                                           fmaxf(acc[mf][nf][1] + b1, 0.f));
            __half2 v1 = __floats2half2_rn(fmaxf(acc[mf][nf][2] + b0, 0.f),
                                           fmaxf(acc[mf][nf][3] + b1, 0.f));
            *(__half2*)(out + (size_t)r0 * NOUT + bn0 + cl) = v0;
            *(__half2*)(out + (size_t)(r0 + 8) * NOUT + bn0 + cl) = v1;
        }
    }
}

// ---------------- combine: all 3 tasks per thread (S read once, fp16 in) -----
__global__ __launch_bounds__(256)
void combine_kernel(float* __restrict__ out)
{
    const size_t idx = (size_t)blockIdx.x * 256 + threadIdx.x;   // b*128 + o4
    const int o4 = (int)(idx & (NOUT / 4 - 1));                  // 0..127
    const int b = (int)(idx >> 7);

    float ge[NTASKS][6];
    #pragma unroll
    for (int t = 0; t < NTASKS; t++) {
        const float* g = g_G + ((size_t)t * MTOK + b) * 6;
        #pragma unroll
        for (int e = 0; e < 6; e++) ge[t][e] = g[e];
    }

    float4 r[NTASKS];
    #pragma unroll
    for (int t = 0; t < NTASKS; t++) r[t] = make_float4(0.f, 0.f, 0.f, 0.f);

    #pragma unroll
    for (int e = 0; e < 4; e++) {
        const __half2* sp = (const __half2*)(g_S + (((size_t)e * MTOK) + b) * NOUT + o4 * 4);
        float2 f0 = __half22float2(sp[0]);
        float2 f1 = __half22float2(sp[1]);
        #pragma unroll
        for (int t = 0; t < NTASKS; t++) {
            r[t].x = fmaf(ge[t][e], f0.x, r[t].x);
            r[t].y = fmaf(ge[t][e], f0.y, r[t].y);
            r[t].z = fmaf(ge[t][e], f1.x, r[t].z);
            r[t].w = fmaf(ge[t][e], f1.y, r[t].w);
        }
    }
    #pragma unroll
    for (int t = 0; t < NTASKS; t++) {
        #pragma unroll
        for (int e = 0; e < 2; e++) {
            const __half2* sp = (const __half2*)(g_T + (((size_t)(t * 2 + e) * MTOK) + b) * NOUT + o4 * 4);
            float2 f0 = __half22float2(sp[0]);
            float2 f1 = __half22float2(sp[1]);
            r[t].x = fmaf(ge[t][4 + e], f0.x, r[t].x);
            r[t].y = fmaf(ge[t][4 + e], f0.y, r[t].y);
            r[t].z = fmaf(ge[t][4 + e], f1.x, r[t].z);
            r[t].w = fmaf(ge[t][4 + e], f1.y, r[t].w);
        }
        *(float4*)(out + (((size_t)t * MTOK + b) * NOUT) + o4 * 4) = r[t];
    }
}

// ---------------- launch -----------------------------------------------------
extern "C" void kernel_launch(void* const* d_in, const int* in_sizes, int n_in,
                              void* d_out, int out_size)
{
    const float* task_inputs = (const float*)d_in[0];
    const float* shared_W    = (const float*)d_in[1];
    const float* shared_b    = (const float*)d_in[2];
    const float* task_W      = (const float*)d_in[3];
    const float* task_b      = (const float*)d_in[4];
    const float* gate_W      = (const float*)d_in[5];
    const float* gate_b      = (const float*)d_in[6];
    float* out = (float*)d_out;

    cudaFuncSetAttribute(gemm_mma_kernel,
                         cudaFuncAttributeMaxDynamicSharedMemorySize, SMEM_BYTES);

    // 1) A fp32 -> fp16
    const size_t atot = (size_t)NTASKS * MTOK * KIN;
    aprep_kernel<<<(unsigned)(atot / 8 / 256), 256>>>(task_inputs);

    // 2) W transpose + fp16
    wprep_kernel<<<dim3(KIN / 32, NOUT / 32, NEXP), 256>>>(shared_W, task_W);

    // 3) fused: 10 expert GEMMs (fp16, 4-stage, B-frag dbuf) + gates (z==10)
    gemm_mma_kernel<<<dim3(NOUT / BN, MTOK / BM, NEXP + 1), 512, SMEM_BYTES>>>(
        task_inputs, shared_b, task_b, gate_W, gate_b);

    // 4) gated combine (fp16 expert outs, all 3 tasks per thread)
    const size_t totalc = (size_t)MTOK * (NOUT / 4);
    combine_kernel<<<(unsigned)(totalc / 256), 256>>>(out);
}

// round 16
// speedup vs baseline: 1.0365x; 1.0365x over previous
#include <cuda_runtime.h>
#include <cuda_fp16.h>
#include <cstdint>
#include <math.h>

#define MTOK 16384
#define NOUT 512
#define KIN  1024
#define NTASKS 3
#define NEXP 10

// ---------------- scratch (device globals; no allocations allowed) ----------
__device__ __half g_S[(size_t)4 * MTOK * NOUT];           // shared-expert outs (fp16)
__device__ __half g_T[(size_t)6 * MTOK * NOUT];           // task-expert outs (fp16)
__device__ float g_G[(size_t)NTASKS * MTOK * 6];          // softmaxed gates
__device__ __half g_W16[(size_t)NEXP * NOUT * KIN];       // W^T fp16, [e][n][k]
__device__ __half g_A16[(size_t)NTASKS * MTOK * KIN];     // A fp16, [t][m][k]

// ---------------- helpers ----------------------------------------------------
__device__ __forceinline__ uint32_t smem_u32(const void* p) {
    uint32_t a;
    asm("{ .reg .u64 t; cvta.to.shared.u64 t, %1; cvt.u32.u64 %0, t; }"
        : "=r"(a) : "l"(p));
    return a;
}
__device__ __forceinline__ uint32_t SW128(uint32_t o) { return o ^ ((o >> 3) & 0x70); }

__device__ __forceinline__ void cp_async16(uint32_t dst, const void* src) {
    asm volatile("cp.async.cg.shared.global [%0], [%1], 16;"
                 :: "r"(dst), "l"(src) : "memory");
}
#define CP_COMMIT() asm volatile("cp.async.commit_group;" ::: "memory")
#define CP_WAIT1()  asm volatile("cp.async.wait_group 1;" ::: "memory")

__device__ __forceinline__ void ldm_x4(uint32_t* r, uint32_t addr) {
    asm volatile("ldmatrix.sync.aligned.m8n8.x4.shared.b16 {%0,%1,%2,%3}, [%4];"
                 : "=r"(r[0]), "=r"(r[1]), "=r"(r[2]), "=r"(r[3]) : "r"(addr));
}
__device__ __forceinline__ void mma_f16(float* c, const uint32_t* a, const uint32_t* b) {
    asm volatile("mma.sync.aligned.m16n8k16.row.col.f32.f16.f16.f32 "
                 "{%0,%1,%2,%3}, {%4,%5,%6,%7}, {%8,%9}, {%0,%1,%2,%3};"
                 : "+f"(c[0]), "+f"(c[1]), "+f"(c[2]), "+f"(c[3])
                 : "r"(a[0]), "r"(a[1]), "r"(a[2]), "r"(a[3]), "r"(b[0]), "r"(b[1]));
}

// ---------------- fused prep: W transpose+fp16 (z<10), A fp32->fp16 (z>=10) --
__global__ __launch_bounds__(256)
void prep_kernel(const float* __restrict__ task_inputs,
                 const float* __restrict__ shared_W,
                 const float* __restrict__ task_W)
{
    const int z = blockIdx.z;
    if (z < NEXP) {
        // W tile transpose: 10 experts x (32x16 grid of 32x32 tiles)
        __shared__ float tile[32][33];
        const float* W = (z < 4) ? shared_W + (size_t)z * KIN * NOUT
                                 : task_W + (size_t)(z - 4) * KIN * NOUT;
        const int k0 = blockIdx.x * 32, n0 = blockIdx.y * 32;
        const int tx = threadIdx.x & 31, ty = threadIdx.x >> 5;

        #pragma unroll
        for (int i = 0; i < 4; i++)
            tile[ty + i * 8][tx] = W[(size_t)(k0 + ty + i * 8) * NOUT + n0 + tx];
        __syncthreads();
        #pragma unroll
        for (int i = 0; i < 4; i++) {
            size_t idx = ((size_t)z * NOUT + (n0 + ty + i * 8)) * KIN + k0 + tx;
            g_W16[idx] = __float2half_rn(tile[tx][ty + i * 8]);
        }
    } else {
        // A conversion: blocks z=10.. cover NTASKS*MTOK*KIN elements, 8/thread
        // linear block id within the A region:
        const size_t blk = (size_t)(z - NEXP) * (gridDim.x * gridDim.y)
                         + blockIdx.y * gridDim.x + blockIdx.x;
        const size_t i = (blk * 256 + threadIdx.x) * 8;
        if (i >= (size_t)NTASKS * MTOK * KIN) return;
        float4 v0 = *(const float4*)(task_inputs + i);
        float4 v1 = *(const float4*)(task_inputs + i + 4);
        __half2 h0 = __floats2half2_rn(v0.x, v0.y);
        __half2 h1 = __floats2half2_rn(v0.z, v0.w);
        __half2 h2 = __floats2half2_rn(v1.x, v1.y);
        __half2 h3 = __floats2half2_rn(v1.z, v1.w);
        uint4 packed = make_uint4(*(uint32_t*)&h0, *(uint32_t*)&h1,
                                  *(uint32_t*)&h2, *(uint32_t*)&h3);
        *(uint4*)(g_A16 + i) = packed;
    }
}

// ---------------- fused GEMM (z<10) + gates (z==10) --------------------------
// GEMM: 128x256 CTA tile fp16, BK=64, 512 threads (16 warps, warp tile 32x64),
// 3 stages + wait_group 1 (R14 mainloop, proven).
#define BM 128
#define BN 256
#define BK 64
#define NKT (KIN / BK)     // 16
#define ST_A 0
#define ST_B 16384
#define STAGE_SZ 49152
#define NSTAGE 3
#define SMEM_BYTES (NSTAGE * STAGE_SZ + 1024)

__global__ __launch_bounds__(512, 1)
void gemm_mma_kernel(const float* __restrict__ task_inputs,
                     const float* __restrict__ shared_b,
                     const float* __restrict__ task_b,
                     const float* __restrict__ gate_W,
                     const float* __restrict__ gate_b)
{
    extern __shared__ char dsm[];
    __shared__ float sbias[BN];

    const int tid = threadIdx.x;
    const int warp = tid >> 5;
    const int lane = tid & 31;
    const int z = blockIdx.z;

    // ======================= gate path (z == 10) ============================
    if (z == 10) {
        float* Wg = (float*)dsm;                       // [KIN][9] padded
        const int blk = blockIdx.y * gridDim.x + blockIdx.x;   // 0..255
        #pragma unroll 1
        for (int t = 0; t < NTASKS; t++) {
            __syncthreads();
            for (int i = tid; i < KIN * 6; i += 512)
                Wg[(i / 6) * 9 + (i % 6)] = gate_W[(size_t)t * KIN * 6 + i];
            __syncthreads();

            #pragma unroll 1
            for (int w = 0; w < 4; w++) {
                const int b = blk * 64 + warp * 4 + w;
                const float* x = task_inputs + ((size_t)t * MTOK + b) * KIN;

                float s[6] = {0.f, 0.f, 0.f, 0.f, 0.f, 0.f};
                #pragma unroll
                for (int i = 0; i < 8; i++) {
                    const int k = i * 128 + lane * 4;
                    float4 xv = *(const float4*)(x + k);
                    float xa[4] = {xv.x, xv.y, xv.z, xv.w};
                    #pragma unroll
                    for (int j = 0; j < 4; j++)
                        #pragma unroll
                        for (int e = 0; e < 6; e++)
                            s[e] = fmaf(xa[j], Wg[(k + j) * 9 + e], s[e]);
                }
                #pragma unroll
                for (int off = 16; off > 0; off >>= 1)
                    #pragma unroll
                    for (int e = 0; e < 6; e++)
                        s[e] += __shfl_xor_sync(0xffffffffu, s[e], off);

                if (lane == 0) {
                    float l[6], mx = -1e30f;
                    #pragma unroll
                    for (int e = 0; e < 6; e++) { l[e] = s[e] + gate_b[t * 6 + e]; mx = fmaxf(mx, l[e]); }
                    float sum = 0.f;
                    #pragma unroll
                    for (int e = 0; e < 6; e++) { l[e] = __expf(l[e] - mx); sum += l[e]; }
                    float inv = 1.f / sum;
                    float* gp = g_G + ((size_t)t * MTOK + b) * 6;
                    #pragma unroll
                    for (int e = 0; e < 6; e++) gp[e] = l[e] * inv;
                }
            }
        }
        return;
    }

    // ======================= GEMM path (z < 10) =============================
    const uint32_t raw = smem_u32(dsm);
    const uint32_t sb = (raw + 1023u) & ~1023u;

    const int bm0 = blockIdx.y * BM;
    const int bn0 = blockIdx.x * BN;

    size_t a_base;
    const float* bias;
    __half* out;
    if (z < 4) {
        a_base = 0;                                  // shared experts: task 0
        bias = shared_b + z * NOUT;
        out = g_S + (size_t)z * MTOK * NOUT;
    } else {
        const int j = z - 4;
        a_base = (size_t)(j >> 1) * MTOK * KIN;
        bias = task_b + j * NOUT;
        out = g_T + (size_t)j * MTOK * NOUT;
    }
    const __half* A = g_A16 + a_base;
    const __half* W = g_W16 + ((size_t)z * NOUT + bn0) * KIN;

    if (tid < BN) sbias[tid] = bias[bn0 + tid];

    // ---- staging: A 16KB (1024 x 16B chunks, 2/thr), B 32KB (2048, 4/thr) --
    uint32_t a_soff[2];
    const __half* a_src[2];
    #pragma unroll
    for (int i = 0; i < 2; i++) {
        int c = tid + 512 * i;
        int row = c >> 3, seg = c & 7;
        a_soff[i] = SW128((uint32_t)(row * 128 + seg * 16));
        a_src[i] = A + (size_t)(bm0 + row) * KIN + seg * 8;
    }
    uint32_t b_soff[4];
    const __half* b_src[4];
    #pragma unroll
    for (int i = 0; i < 4; i++) {
        int c = tid + 512 * i;
        int row = c >> 3, seg = c & 7;
        b_soff[i] = SW128((uint32_t)(row * 128 + seg * 16));
        b_src[i] = W + (size_t)row * KIN + seg * 8;
    }

    // warp tiling: 4(M) x 4(N); warp tile 32x64
    const int wm = warp & 3, wn = warp >> 2;
    const int m_base = wm * 32;
    const int n_base = wn * 64;
    const int lr16 = lane & 15, lc16 = (lane >> 4) << 4;

    uint32_t a_lbase[2];
    #pragma unroll
    for (int mf = 0; mf < 2; mf++)
        a_lbase[mf] = (uint32_t)((m_base + mf * 16 + lr16) * 128 + lc16);
    uint32_t b_lbase[4];
    #pragma unroll
    for (int p = 0; p < 4; p++)
        b_lbase[p] = (uint32_t)((n_base + p * 16 + lr16) * 128 + lc16);

    float acc[2][8][4];
    #pragma unroll
    for (int mf = 0; mf < 2; mf++)
        #pragma unroll
        for (int nf = 0; nf < 8; nf++)
            #pragma unroll
            for (int r = 0; r < 4; r++) acc[mf][nf][r] = 0.f;

    auto issue = [&](int kt, int s) {
        const uint32_t sa = sb + s * STAGE_SZ;
        const int ko = kt * BK;
        #pragma unroll
        for (int i = 0; i < 2; i++)
            cp_async16(sa + ST_A + a_soff[i], a_src[i] + ko);
        #pragma unroll
        for (int i = 0; i < 4; i++)
            cp_async16(sa + ST_B + b_soff[i], b_src[i] + ko);
    };

    issue(0, 0); CP_COMMIT();
    issue(1, 1); CP_COMMIT();

    int buf = 0, nxt = 2;
    #pragma unroll 1
    for (int kt = 0; kt < NKT; kt++) {
        CP_WAIT1();
        __syncthreads();

        if (kt + 2 < NKT) issue(kt + 2, nxt);
        CP_COMMIT();

        const uint32_t ab = sb + buf * STAGE_SZ;
        buf = (buf == 2) ? 0 : buf + 1;
        nxt = (nxt == 2) ? 0 : nxt + 1;

        #pragma unroll
        for (int ks = 0; ks < 4; ks++) {
            // b16 ldmatrix reg->fragment map (validated in R6/R13):
            //   n8-block even = {r0, r2}, n8-block odd = {r1, r3}
            uint32_t afr[2][4], bfr[8][2];
            #pragma unroll
            for (int mf = 0; mf < 2; mf++)
                ldm_x4(afr[mf], ab + ST_A + SW128(a_lbase[mf] + ks * 32));
            #pragma unroll
            for (int p = 0; p < 4; p++) {
                uint32_t r[4];
                ldm_x4(r, ab + ST_B + SW128(b_lbase[p] + ks * 32));
                bfr[2 * p][0] = r[0];     bfr[2 * p + 1][0] = r[1];
                bfr[2 * p][1] = r[2];     bfr[2 * p + 1][1] = r[3];
            }
            #pragma unroll
            for (int mf = 0; mf < 2; mf++)
                #pragma unroll
                for (int nf = 0; nf < 8; nf++)
                    mma_f16(acc[mf][nf], afr[mf], bfr[nf]);
        }
    }

    // ---- epilogue: bias + relu + fp16 store ----
    const int gq = lane >> 2, i2 = (lane & 3) * 2;
    #pragma unroll
    for (int mf = 0; mf < 2; mf++) {
        const int r0 = bm0 + m_base + mf * 16 + gq;
        #pragma unroll
        for (int nf = 0; nf < 8; nf++) {
            const int cl = n_base + nf * 8 + i2;
            const float b0 = sbias[cl], b1 = sbias[cl + 1];
            __half2 v0 = __floats2half2_rn(fmaxf(acc[mf][nf][0] + b0, 0.f),
                                           fmaxf(acc[mf][nf][1] + b1, 0.f));
            __half2 v1 = __floats2half2_rn(fmaxf(acc[mf][nf][2] + b0, 0.f),
                                           fmaxf(acc[mf][nf][3] + b1, 0.f));
            *(__half2*)(out + (size_t)r0 * NOUT + bn0 + cl) = v0;
            *(__half2*)(out + (size_t)(r0 + 8) * NOUT + bn0 + cl) = v1;
        }
    }
}

// ---------------- combine: 2 o4-chunks x 3 tasks per thread ------------------
__global__ __launch_bounds__(256)
void combine_kernel(float* __restrict__ out)
{
    // Each thread handles token b at o4 and o4+64 (two float4 chunks).
    const size_t idx = (size_t)blockIdx.x * 256 + threadIdx.x;   // b*64 + o4
    const int o4 = (int)(idx & 63);                              // 0..63
    const int b = (int)(idx >> 6);

    float ge[NTASKS][6];
    #pragma unroll
    for (int t = 0; t < NTASKS; t++) {
        const float* g = g_G + ((size_t)t * MTOK + b) * 6;
        #pragma unroll
        for (int e = 0; e < 6; e++) ge[t][e] = g[e];
    }

    float4 r[2][NTASKS];
    #pragma unroll
    for (int c = 0; c < 2; c++)
        #pragma unroll
        for (int t = 0; t < NTASKS; t++) r[c][t] = make_float4(0.f, 0.f, 0.f, 0.f);

    #pragma unroll
    for (int e = 0; e < 4; e++) {
        const __half2* sp0 = (const __half2*)(g_S + (((size_t)e * MTOK) + b) * NOUT + o4 * 4);
        const __half2* sp1 = sp0 + 128;   // +64 floats = +128 halves = 64 half2... (o4+64)*4 halves
        #pragma unroll
        for (int c = 0; c < 2; c++) {
            const __half2* sp = c ? sp1 : sp0;
            float2 f0 = __half22float2(sp[0]);
            float2 f1 = __half22float2(sp[1]);
            #pragma unroll
            for (int t = 0; t < NTASKS; t++) {
                r[c][t].x = fmaf(ge[t][e], f0.x, r[c][t].x);
                r[c][t].y = fmaf(ge[t][e], f0.y, r[c][t].y);
                r[c][t].z = fmaf(ge[t][e], f1.x, r[c][t].z);
                r[c][t].w = fmaf(ge[t][e], f1.y, r[c][t].w);
            }
        }
    }
    #pragma unroll
    for (int t = 0; t < NTASKS; t++) {
        #pragma unroll
        for (int e = 0; e < 2; e++) {
            const __half2* sp0 = (const __half2*)(g_T + (((size_t)(t * 2 + e) * MTOK) + b) * NOUT + o4 * 4);
            #pragma unroll
            for (int c = 0; c < 2; c++) {
                const __half2* sp = sp0 + c * 128;
                float2 f0 = __half22float2(sp[0]);
                float2 f1 = __half22float2(sp[1]);
                r[c][t].x = fmaf(ge[t][4 + e], f0.x, r[c][t].x);
                r[c][t].y = fmaf(ge[t][4 + e], f0.y, r[c][t].y);
                r[c][t].z = fmaf(ge[t][4 + e], f1.x, r[c][t].z);
                r[c][t].w = fmaf(ge[t][4 + e], f1.y, r[c][t].w);
            }
        }
        float* op = out + ((size_t)t * MTOK + b) * NOUT + o4 * 4;
        *(float4*)op = r[0][t];
        *(float4*)(op + 256) = r[1][t];
    }
}

// ---------------- launch -----------------------------------------------------
extern "C" void kernel_launch(void* const* d_in, const int* in_sizes, int n_in,
                              void* d_out, int out_size)
{
    const float* task_inputs = (const float*)d_in[0];
    const float* shared_W    = (const float*)d_in[1];
    const float* shared_b    = (const float*)d_in[2];
    const float* task_W      = (const float*)d_in[3];
    const float* task_b      = (const float*)d_in[4];
    const float* gate_W      = (const float*)d_in[5];
    const float* gate_b      = (const float*)d_in[6];
    float* out = (float*)d_out;

    cudaFuncSetAttribute(gemm_mma_kernel,
                         cudaFuncAttributeMaxDynamicSharedMemorySize, SMEM_BYTES);

    // 1) fused prep: W transpose+fp16 (z=0..9) + A fp32->fp16 (z=10..)
    //    W grid per z: 32 x 16 blocks. A needs 24576 blocks of 256thr*8elem
    //    = ceil(24576 / (32*16)) = 48 z-slices.
    prep_kernel<<<dim3(KIN / 32, NOUT / 32, NEXP + 48), 256>>>(
        task_inputs, shared_W, task_W);

    // 2) fused: 10 expert GEMMs (fp16, R14 mainloop) + gates (z==10)
    gemm_mma_kernel<<<dim3(NOUT / BN, MTOK / BM, NEXP + 1), 512, SMEM_BYTES>>>(
        task_inputs, shared_b, task_b, gate_W, gate_b);

    // 3) gated combine (2 chunks/thread)
    const size_t totalc = (size_t)MTOK * 64;
    combine_kernel<<<(unsigned)(totalc / 256), 256>>>(out);
}

// round 17
// speedup vs baseline: 1.1823x; 1.1407x over previous
#include <cuda_runtime.h>
#include <cuda_fp16.h>
#include <cstdint>
#include <math.h>

#define MTOK 16384
#define NOUT 512
#define KIN  1024
#define NTASKS 3
#define NEXP 10

// ---------------- scratch (device globals; no allocations allowed) ----------
__device__ __half g_S[(size_t)4 * MTOK * NOUT];           // shared-expert outs (fp16)
__device__ __half g_T[(size_t)6 * MTOK * NOUT];           // task-expert outs (fp16)
__device__ float g_G[(size_t)NTASKS * MTOK * 6];          // softmaxed gates
__device__ __half g_W16[(size_t)NEXP * NOUT * KIN];       // W^T fp16, [e][n][k]
__device__ __half g_A16[(size_t)NTASKS * MTOK * KIN];     // A fp16, [t][m][k]

// ---------------- helpers ----------------------------------------------------
__device__ __forceinline__ uint32_t smem_u32(const void* p) {
    uint32_t a;
    asm("{ .reg .u64 t; cvta.to.shared.u64 t, %1; cvt.u32.u64 %0, t; }"
        : "=r"(a) : "l"(p));
    return a;
}
__device__ __forceinline__ uint32_t SW128(uint32_t o) { return o ^ ((o >> 3) & 0x70); }

__device__ __forceinline__ void cp_async16(uint32_t dst, const void* src) {
    asm volatile("cp.async.cg.shared.global [%0], [%1], 16;"
                 :: "r"(dst), "l"(src) : "memory");
}
#define CP_COMMIT() asm volatile("cp.async.commit_group;" ::: "memory")
#define CP_WAIT1()  asm volatile("cp.async.wait_group 1;" ::: "memory")

__device__ __forceinline__ void ldm_x4(uint32_t* r, uint32_t addr) {
    asm volatile("ldmatrix.sync.aligned.m8n8.x4.shared.b16 {%0,%1,%2,%3}, [%4];"
                 : "=r"(r[0]), "=r"(r[1]), "=r"(r[2]), "=r"(r[3]) : "r"(addr));
}
__device__ __forceinline__ void mma_f16(float* c, const uint32_t* a, const uint32_t* b) {
    asm volatile("mma.sync.aligned.m16n8k16.row.col.f32.f16.f16.f32 "
                 "{%0,%1,%2,%3}, {%4,%5,%6,%7}, {%8,%9}, {%0,%1,%2,%3};"
                 : "+f"(c[0]), "+f"(c[1]), "+f"(c[2]), "+f"(c[3])
                 : "r"(a[0]), "r"(a[1]), "r"(a[2]), "r"(a[3]), "r"(b[0]), "r"(b[1]));
}

// ---------------- W prep: transpose + fp16 -----------------------------------
__global__ __launch_bounds__(256)
void wprep_kernel(const float* __restrict__ shared_W, const float* __restrict__ task_W)
{
    __shared__ float tile[32][33];
    const int e = blockIdx.z;
    const float* W = (e < 4) ? shared_W + (size_t)e * KIN * NOUT
                             : task_W + (size_t)(e - 4) * KIN * NOUT;
    const int k0 = blockIdx.x * 32, n0 = blockIdx.y * 32;
    const int tx = threadIdx.x & 31, ty = threadIdx.x >> 5;

    #pragma unroll
    for (int i = 0; i < 4; i++)
        tile[ty + i * 8][tx] = W[(size_t)(k0 + ty + i * 8) * NOUT + n0 + tx];
    __syncthreads();
    #pragma unroll
    for (int i = 0; i < 4; i++) {
        size_t idx = ((size_t)e * NOUT + (n0 + ty + i * 8)) * KIN + k0 + tx;
        g_W16[idx] = __float2half_rn(tile[tx][ty + i * 8]);
    }
}

// ---------------- gates + A fp32->fp16 (x read once) -------------------------
// Block = (32 tokens, 1 task). 256 threads / 8 warps, 4 tokens per warp.
// Also converts those 32 A rows to fp16 (x is L1/L2-hot from the gate loads).
__global__ __launch_bounds__(256)
void gate_aconv_kernel(const float* __restrict__ task_inputs,
                       const float* __restrict__ gate_W,
                       const float* __restrict__ gate_b)
{
    __shared__ float Wg[KIN][9];
    const int t = blockIdx.y;
    for (int i = threadIdx.x; i < KIN * 6; i += 256)
        Wg[i / 6][i % 6] = gate_W[(size_t)t * KIN * 6 + i];
    __syncthreads();

    const int warp = threadIdx.x >> 5, lane = threadIdx.x & 31;
    const int b0 = blockIdx.x * 32;

    // ---- gates: 4 tokens per warp ----
    #pragma unroll 1
    for (int w = 0; w < 4; w++) {
        const int b = b0 + warp * 4 + w;
        const float* x = task_inputs + ((size_t)t * MTOK + b) * KIN;

        float s[6] = {0.f, 0.f, 0.f, 0.f, 0.f, 0.f};
        #pragma unroll
        for (int i = 0; i < 8; i++) {
            const int k = i * 128 + lane * 4;
            float4 xv = *(const float4*)(x + k);
            float xa[4] = {xv.x, xv.y, xv.z, xv.w};
            #pragma unroll
            for (int j = 0; j < 4; j++)
                #pragma unroll
                for (int e = 0; e < 6; e++)
                    s[e] = fmaf(xa[j], Wg[k + j][e], s[e]);
        }
        #pragma unroll
        for (int off = 16; off > 0; off >>= 1)
            #pragma unroll
            for (int e = 0; e < 6; e++)
                s[e] += __shfl_xor_sync(0xffffffffu, s[e], off);

        if (lane == 0) {
            float l[6], mx = -1e30f;
            #pragma unroll
            for (int e = 0; e < 6; e++) { l[e] = s[e] + gate_b[t * 6 + e]; mx = fmaxf(mx, l[e]); }
            float sum = 0.f;
            #pragma unroll
            for (int e = 0; e < 6; e++) { l[e] = __expf(l[e] - mx); sum += l[e]; }
            float inv = 1.f / sum;
            float* gp = g_G + ((size_t)t * MTOK + b) * 6;
            #pragma unroll
            for (int e = 0; e < 6; e++) gp[e] = l[e] * inv;
        }
    }

    // ---- A conversion for these 32 rows: 32*1024 elems, 8/thread/iter ----
    const size_t base = ((size_t)t * MTOK + b0) * KIN;
    #pragma unroll
    for (int it = 0; it < 16; it++) {
        const size_t i = base + ((size_t)it * 256 + threadIdx.x) * 8;
        float4 v0 = *(const float4*)(task_inputs + i);
        float4 v1 = *(const float4*)(task_inputs + i + 4);
        __half2 h0 = __floats2half2_rn(v0.x, v0.y);
        __half2 h1 = __floats2half2_rn(v0.z, v0.w);
        __half2 h2 = __floats2half2_rn(v1.x, v1.y);
        __half2 h3 = __floats2half2_rn(v1.z, v1.w);
        uint4 packed = make_uint4(*(uint32_t*)&h0, *(uint32_t*)&h1,
                                  *(uint32_t*)&h2, *(uint32_t*)&h3);
        *(uint4*)(g_A16 + i) = packed;
    }
}

// ---------------- GEMM: 128x256 fp16, BK=64, 16 warps, 3 stages (R14) -------
#define BM 128
#define BN 256
#define BK 64
#define NKT (KIN / BK)     // 16
#define ST_A 0
#define ST_B 16384
#define STAGE_SZ 49152
#define NSTAGE 3
#define SMEM_BYTES (NSTAGE * STAGE_SZ + 1024)

__global__ __launch_bounds__(512, 1)
void gemm_mma_kernel(const float* __restrict__ shared_b,
                     const float* __restrict__ task_b)
{
    extern __shared__ char dsm[];
    __shared__ float sbias[BN];

    const int tid = threadIdx.x;
    const int warp = tid >> 5;
    const int lane = tid & 31;
    const int z = blockIdx.z;

    const uint32_t raw = smem_u32(dsm);
    const uint32_t sb = (raw + 1023u) & ~1023u;

    const int bm0 = blockIdx.y * BM;
    const int bn0 = blockIdx.x * BN;

    size_t a_base;
    const float* bias;
    __half* out;
    if (z < 4) {
        a_base = 0;                                  // shared experts: task 0
        bias = shared_b + z * NOUT;
        out = g_S + (size_t)z * MTOK * NOUT;
    } else {
        const int j = z - 4;
        a_base = (size_t)(j >> 1) * MTOK * KIN;
        bias = task_b + j * NOUT;
        out = g_T + (size_t)j * MTOK * NOUT;
    }
    const __half* A = g_A16 + a_base;
    const __half* W = g_W16 + ((size_t)z * NOUT + bn0) * KIN;

    if (tid < BN) sbias[tid] = bias[bn0 + tid];

    // ---- staging: A 16KB (1024 x 16B chunks, 2/thr), B 32KB (2048, 4/thr) --
    uint32_t a_soff[2];
    const __half* a_src[2];
    #pragma unroll
    for (int i = 0; i < 2; i++) {
        int c = tid + 512 * i;
        int row = c >> 3, seg = c & 7;
        a_soff[i] = SW128((uint32_t)(row * 128 + seg * 16));
        a_src[i] = A + (size_t)(bm0 + row) * KIN + seg * 8;
    }
    uint32_t b_soff[4];
    const __half* b_src[4];
    #pragma unroll
    for (int i = 0; i < 4; i++) {
        int c = tid + 512 * i;
        int row = c >> 3, seg = c & 7;
        b_soff[i] = SW128((uint32_t)(row * 128 + seg * 16));
        b_src[i] = W + (size_t)row * KIN + seg * 8;
    }

    // warp tiling: 4(M) x 4(N); warp tile 32x64
    const int wm = warp & 3, wn = warp >> 2;
    const int m_base = wm * 32;
    const int n_base = wn * 64;
    const int lr16 = lane & 15, lc16 = (lane >> 4) << 4;

    uint32_t a_lbase[2];
    #pragma unroll
    for (int mf = 0; mf < 2; mf++)
        a_lbase[mf] = (uint32_t)((m_base + mf * 16 + lr16) * 128 + lc16);
    uint32_t b_lbase[4];
    #pragma unroll
    for (int p = 0; p < 4; p++)
        b_lbase[p] = (uint32_t)((n_base + p * 16 + lr16) * 128 + lc16);

    float acc[2][8][4];
    #pragma unroll
    for (int mf = 0; mf < 2; mf++)
        #pragma unroll
        for (int nf = 0; nf < 8; nf++)
            #pragma unroll
            for (int r = 0; r < 4; r++) acc[mf][nf][r] = 0.f;

    auto issue = [&](int kt, int s) {
        const uint32_t sa = sb + s * STAGE_SZ;
        const int ko = kt * BK;
        #pragma unroll
        for (int i = 0; i < 2; i++)
            cp_async16(sa + ST_A + a_soff[i], a_src[i] + ko);
        #pragma unroll
        for (int i = 0; i < 4; i++)
            cp_async16(sa + ST_B + b_soff[i], b_src[i] + ko);
    };

    issue(0, 0); CP_COMMIT();
    issue(1, 1); CP_COMMIT();

    int buf = 0, nxt = 2;
    #pragma unroll 1
    for (int kt = 0; kt < NKT; kt++) {
        CP_WAIT1();
        __syncthreads();

        if (kt + 2 < NKT) issue(kt + 2, nxt);
        CP_COMMIT();

        const uint32_t ab = sb + buf * STAGE_SZ;
        buf = (buf == 2) ? 0 : buf + 1;
        nxt = (nxt == 2) ? 0 : nxt + 1;

        #pragma unroll
        for (int ks = 0; ks < 4; ks++) {
            // b16 ldmatrix reg->fragment map (validated in R6/R13):
            //   n8-block even = {r0, r2}, n8-block odd = {r1, r3}
            uint32_t afr[2][4], bfr[8][2];
            #pragma unroll
            for (int mf = 0; mf < 2; mf++)
                ldm_x4(afr[mf], ab + ST_A + SW128(a_lbase[mf] + ks * 32));
            #pragma unroll
            for (int p = 0; p < 4; p++) {
                uint32_t r[4];
                ldm_x4(r, ab + ST_B + SW128(b_lbase[p] + ks * 32));
                bfr[2 * p][0] = r[0];     bfr[2 * p + 1][0] = r[1];
                bfr[2 * p][1] = r[2];     bfr[2 * p + 1][1] = r[3];
            }
            #pragma unroll
            for (int mf = 0; mf < 2; mf++)
                #pragma unroll
                for (int nf = 0; nf < 8; nf++)
                    mma_f16(acc[mf][nf], afr[mf], bfr[nf]);
        }
    }

    // ---- epilogue: bias + relu + fp16 store ----
    const int gq = lane >> 2, i2 = (lane & 3) * 2;
    #pragma unroll
    for (int mf = 0; mf < 2; mf++) {
        const int r0 = bm0 + m_base + mf * 16 + gq;
        #pragma unroll
        for (int nf = 0; nf < 8; nf++) {
            const int cl = n_base + nf * 8 + i2;
            const float b0 = sbias[cl], b1 = sbias[cl + 1];
            __half2 v0 = __floats2half2_rn(fmaxf(acc[mf][nf][0] + b0, 0.f),
                                           fmaxf(acc[mf][nf][1] + b1, 0.f));
            __half2 v1 = __floats2half2_rn(fmaxf(acc[mf][nf][2] + b0, 0.f),
                                           fmaxf(acc[mf][nf][3] + b1, 0.f));
            *(__half2*)(out + (size_t)r0 * NOUT + bn0 + cl) = v0;
            *(__half2*)(out + (size_t)(r0 + 8) * NOUT + bn0 + cl) = v1;
        }
    }
}

// ---------------- combine: 2 o4-chunks x 3 tasks per thread ------------------
__global__ __launch_bounds__(256)
void combine_kernel(float* __restrict__ out)
{
    const size_t idx = (size_t)blockIdx.x * 256 + threadIdx.x;   // b*64 + o4
    const int o4 = (int)(idx & 63);                              // 0..63
    const int b = (int)(idx >> 6);

    float ge[NTASKS][6];
    #pragma unroll
    for (int t = 0; t < NTASKS; t++) {
        const float* g = g_G + ((size_t)t * MTOK + b) * 6;
        #pragma unroll
        for (int e = 0; e < 6; e++) ge[t][e] = g[e];
    }

    float4 r[2][NTASKS];
    #pragma unroll
    for (int c = 0; c < 2; c++)
        #pragma unroll
        for (int t = 0; t < NTASKS; t++) r[c][t] = make_float4(0.f, 0.f, 0.f, 0.f);

    #pragma unroll
    for (int e = 0; e < 4; e++) {
        const __half2* sp0 = (const __half2*)(g_S + (((size_t)e * MTOK) + b) * NOUT + o4 * 4);
        #pragma unroll
        for (int c = 0; c < 2; c++) {
            const __half2* sp = sp0 + c * 128;
            float2 f0 = __half22float2(sp[0]);
            float2 f1 = __half22float2(sp[1]);
            #pragma unroll
            for (int t = 0; t < NTASKS; t++) {
                r[c][t].x = fmaf(ge[t][e], f0.x, r[c][t].x);
                r[c][t].y = fmaf(ge[t][e], f0.y, r[c][t].y);
                r[c][t].z = fmaf(ge[t][e], f1.x, r[c][t].z);
                r[c][t].w = fmaf(ge[t][e], f1.y, r[c][t].w);
            }
        }
    }
    #pragma unroll
    for (int t = 0; t < NTASKS; t++) {
        #pragma unroll
        for (int e = 0; e < 2; e++) {
            const __half2* sp0 = (const __half2*)(g_T + (((size_t)(t * 2 + e) * MTOK) + b) * NOUT + o4 * 4);
            #pragma unroll
            for (int c = 0; c < 2; c++) {
                const __half2* sp = sp0 + c * 128;
                float2 f0 = __half22float2(sp[0]);
                float2 f1 = __half22float2(sp[1]);
                r[c][t].x = fmaf(ge[t][4 + e], f0.x, r[c][t].x);
                r[c][t].y = fmaf(ge[t][4 + e], f0.y, r[c][t].y);
                r[c][t].z = fmaf(ge[t][4 + e], f1.x, r[c][t].z);
                r[c][t].w = fmaf(ge[t][4 + e], f1.y, r[c][t].w);
            }
        }
        float* op = out + ((size_t)t * MTOK + b) * NOUT + o4 * 4;
        *(float4*)op = r[0][t];
        *(float4*)(op + 256) = r[1][t];
    }
}

// ---------------- launch -----------------------------------------------------
extern "C" void kernel_launch(void* const* d_in, const int* in_sizes, int n_in,
                              void* d_out, int out_size)
{
    const float* task_inputs = (const float*)d_in[0];
    const float* shared_W    = (const float*)d_in[1];
    const float* shared_b    = (const float*)d_in[2];
    const float* task_W      = (const float*)d_in[3];
    const float* task_b      = (const float*)d_in[4];
    const float* gate_W      = (const float*)d_in[5];
    const float* gate_b      = (const float*)d_in[6];
    float* out = (float*)d_out;

    cudaFuncSetAttribute(gemm_mma_kernel,
                         cudaFuncAttributeMaxDynamicSharedMemorySize, SMEM_BYTES);

    // 1) W transpose + fp16 (small)
    wprep_kernel<<<dim3(KIN / 32, NOUT / 32, NEXP), 256>>>(shared_W, task_W);

    // 2) gates + A conversion (task_inputs read exactly once)
    gate_aconv_kernel<<<dim3(MTOK / 32, NTASKS), 256>>>(task_inputs, gate_W, gate_b);

    // 3) 10 expert GEMMs (fp16, R14 mainloop)
    gemm_mma_kernel<<<dim3(NOUT / BN, MTOK / BM, NEXP), 512, SMEM_BYTES>>>(
        shared_b, task_b);

    // 4) gated combine (2 chunks/thread)
    const size_t totalc = (size_t)MTOK * 64;
    combine_kernel<<<(unsigned)(totalc / 256), 256>>>(out);
}